// round 8
// baseline (speedup 1.0000x reference)
#include <cuda_runtime.h>
#include <cuda_bf16.h>
#include <math.h>
#include <stdint.h>

// ---------------- problem constants ----------------
#define BB    512
#define TT    64
#define EMBD  512
#define HIDD  1024
#define NG    4096
#define NOUT  2048
#define KIN   (EMBD + HIDD)     // 1536
#define KG    (3 * KIN)         // 4608  (split K', gates)
#define KO    (3 * HIDD)        // 3072  (split K', output proj; also g_Ah row length)
#define NCHUNK_G (KG / 64)      // 72  (first 24 chunks = emb piece, rest = h piece)
#define NCHUNK_O (KO / 64)      // 48
#define SMEM_DYN (3 * 32768 + 256)

// ---------------- persistent device scratch ----------------
__device__ float g_c[BB * HIDD];
__device__ float g_bias[NG];                                  // interleaved b_ih+b_hh
__device__ __align__(16) __nv_bfloat16 g_Ah[2][BB * KO];      // [hh|hl|hh] per row, ping-pong
__device__ __align__(16) __nv_bfloat16 g_Aemb[(size_t)TT * BB * KIN]; // per (t,b): [xh|xl|xh]
__device__ __align__(16) __nv_bfloat16 g_Wg[(size_t)NG * KG]; // gate-interleaved rows
__device__ __align__(16) __nv_bfloat16 g_Wo[(size_t)NOUT * KO];

// ---------------- helpers ----------------
__device__ __forceinline__ uint32_t smem_u32(const void* p) {
    uint32_t a;
    asm("{ .reg .u64 t; cvta.to.shared.u64 t, %1; cvt.u32.u64 %0, t; }" : "=r"(a) : "l"(p));
    return a;
}
__device__ __forceinline__ void split_bf16(float v, __nv_bfloat16& hi, __nv_bfloat16& lo) {
    hi = __float2bfloat16(v);
    lo = __float2bfloat16(v - __bfloat162float(hi));
}
__device__ __forceinline__ void cp_async16(uint32_t dst, const void* src) {
    asm volatile("cp.async.cg.shared.global [%0], [%1], 16;" :: "r"(dst), "l"(src));
}
__device__ __forceinline__ void cp_commit() {
    asm volatile("cp.async.commit_group;" ::: "memory");
}
__device__ __forceinline__ void ldsm_x4(uint32_t* r, uint32_t addr) {
    asm volatile("ldmatrix.sync.aligned.m8n8.x4.shared.b16 {%0,%1,%2,%3}, [%4];"
                 : "=r"(r[0]), "=r"(r[1]), "=r"(r[2]), "=r"(r[3]) : "r"(addr));
}
__device__ __forceinline__ void mma16816(float* d, const uint32_t* a, uint32_t b0, uint32_t b1) {
    asm volatile(
        "mma.sync.aligned.m16n8k16.row.col.f32.bf16.bf16.f32 "
        "{%0,%1,%2,%3}, {%4,%5,%6,%7}, {%8,%9}, {%0,%1,%2,%3};"
        : "+f"(d[0]), "+f"(d[1]), "+f"(d[2]), "+f"(d[3])
        : "r"(a[0]), "r"(a[1]), "r"(a[2]), "r"(a[3]), "r"(b0), "r"(b1));
}
__device__ __forceinline__ float sigmoidf_(float x) { return 1.0f / (1.0f + expf(-x)); }

// ---------------- setup kernels ----------------
__global__ void init_state_kernel() {
    int i = blockIdx.x * 256 + threadIdx.x;     // grid covers 786432
    if (i < BB * HIDD) g_c[i] = 0.0f;
    ((uint32_t*)g_Ah)[i] = 0u;                  // 2*BB*KO bf16 = 786432 u32 (both buffers)
}

__global__ void bias_kernel(const float* __restrict__ b_ih, const float* __restrict__ b_hh) {
    int n_ = blockIdx.x * 256 + threadIdx.x;    // n' interleaved
    int gate = n_ & 3, j = n_ >> 2;
    g_bias[n_] = b_ih[gate * HIDD + j] + b_hh[gate * HIDD + j];
}

// W'g row n' = 4j+gate :  [Wih_h(512) | Wih_h | Wih_l | Whh_h(1024) | Whh_h | Whh_l]
__global__ void conv_wg_kernel(const float* __restrict__ W_ih, const float* __restrict__ W_hh) {
    int idx = blockIdx.x * 256 + threadIdx.x;   // NG*KIN
    int n_ = idx / KIN, k = idx - n_ * KIN;
    int gate = n_ & 3, j = n_ >> 2;
    int orig = gate * HIDD + j;
    size_t r = (size_t)n_ * KG;
    if (k < EMBD) {
        __nv_bfloat16 hi, lo; split_bf16(W_ih[(size_t)orig * EMBD + k], hi, lo);
        g_Wg[r + k] = hi; g_Wg[r + EMBD + k] = hi; g_Wg[r + 2 * EMBD + k] = lo;
    } else {
        int kh = k - EMBD;
        __nv_bfloat16 hi, lo; split_bf16(W_hh[(size_t)orig * HIDD + kh], hi, lo);
        g_Wg[r + 3 * EMBD + kh] = hi;
        g_Wg[r + 3 * EMBD + HIDD + kh] = hi;
        g_Wg[r + 3 * EMBD + 2 * HIDD + kh] = lo;
    }
}

__global__ void conv_wo_kernel(const float* __restrict__ W_out) {
    int idx = blockIdx.x * 256 + threadIdx.x;   // NOUT*HIDD
    int n = idx / HIDD, k = idx - n * HIDD;
    __nv_bfloat16 hi, lo; split_bf16(W_out[(size_t)n * HIDD + k], hi, lo);
    size_t r = (size_t)n * KO;
    g_Wo[r + k] = hi; g_Wo[r + HIDD + k] = hi; g_Wo[r + 2 * HIDD + k] = lo;
}

// Precompute x-part of A' for all steps: per (t,b): [xh | xl | xh]
__global__ void emb_precompute_kernel(const int* __restrict__ tok, const float* __restrict__ emb) {
    size_t idx = (size_t)blockIdx.x * 256 + threadIdx.x;   // TT*BB*EMBD
    int t = (int)(idx / (BB * EMBD));
    int rem = (int)(idx - (size_t)t * BB * EMBD);
    int b = rem / EMBD, k = rem - b * EMBD;
    float v = emb[(size_t)tok[b * TT + t] * EMBD + k];
    __nv_bfloat16 hi, lo; split_bf16(v, hi, lo);
    size_t r = ((size_t)t * BB + b) * KIN;
    g_Aemb[r + k] = hi; g_Aemb[r + EMBD + k] = lo; g_Aemb[r + 2 * EMBD + k] = hi;
}

// ---------------- fused GEMM (+ LSTM pointwise epilogue for MODE 0) ----------------
// CTA 128x128, 8 warps (2x4), warp tile 64x32, K-slab 64 (128B rows, SW128 swizzle),
// 3-stage cp.async, register double-buffered fragments.
template <int MODE>   // 0 = gates+LSTM (no C output), 1 = output proj (C=Cout, +bias)
__global__ __launch_bounds__(256, 1) void mma_gemm(float* __restrict__ Cout,
                                                   const float* __restrict__ biasO,
                                                   int t, int par) {
    constexpr int NCHUNK = (MODE == 0) ? NCHUNK_G : NCHUNK_O;
    constexpr int KLB    = (MODE == 0) ? KG : KO;
    const __nv_bfloat16* Bw = (MODE == 0) ? g_Wg : g_Wo;

    extern __shared__ char dyn[];
    const uint32_t sbase = (smem_u32(dyn) + 127u) & ~127u;
    // stage s (s<3): A tile at sbase + s*32768, B tile at +16384

    const int tid  = threadIdx.x;
    const int wid  = tid >> 5, lane = tid & 31;
    const int m0 = blockIdx.y * 128, n0 = blockIdx.x * 128;
    const int w_m = (wid >> 2) * 64;
    const int w_n = (wid & 3) * 32;

    // ----- cp.async loader -----
    const int lr  = tid >> 3;         // 0..31
    const int lsB = (tid & 7) * 16;   // byte seg within 128B row
    const __nv_bfloat16* Ah = g_Ah[(MODE == 0) ? par : 0];
    auto issue = [&](int kc) {
        const uint32_t st = sbase + (kc % 3) * 32768;
        const __nv_bfloat16* ag;
        size_t klda;
        if (MODE == 0) {
            if (kc < 24) { ag = g_Aemb + ((size_t)t * BB + (m0 + lr)) * KIN + kc * 64 + (lsB >> 1); klda = KIN; }
            else         { ag = Ah + (size_t)(m0 + lr) * KO + (kc - 24) * 64 + (lsB >> 1);          klda = KO;  }
        } else {
            ag = Ah + (size_t)(m0 + lr) * KO + kc * 64 + (lsB >> 1); klda = KO;
        }
        const __nv_bfloat16* bg = Bw + (size_t)(n0 + lr) * KLB + kc * 64 + (lsB >> 1);
#pragma unroll
        for (int i = 0; i < 4; i++) {
            uint32_t off = (uint32_t)(lr + i * 32) * 128u + (uint32_t)lsB;
            uint32_t sw  = off ^ ((off >> 3) & 0x70u);
            cp_async16(st + sw, ag + (size_t)i * 32 * klda);
            cp_async16(st + 16384 + sw, bg + (size_t)i * 32 * KLB);
        }
        cp_commit();
    };

    // ----- per-lane ldmatrix base offsets (pre-swizzle) -----
    const int q  = lane >> 3;
    const int r8 = lane & 7;
    const uint32_t arow = (uint32_t)(w_m + (q & 1) * 8 + r8);
    const uint32_t akb  = (uint32_t)((q >> 1) * 16);
    const uint32_t brow = (uint32_t)(w_n + (q >> 1) * 8 + r8);
    const uint32_t bkb  = (uint32_t)((q & 1) * 16);

    float acc[4][4][4];
#pragma unroll
    for (int i = 0; i < 4; i++)
#pragma unroll
        for (int j = 0; j < 4; j++)
#pragma unroll
            for (int v = 0; v < 4; v++) acc[i][j][v] = 0.0f;

    issue(0);
    issue(1);

    uint32_t afr[2][4][4], bfr[2][2][4];

    for (int kc = 0; kc < NCHUNK; kc++) {
        if (kc + 1 < NCHUNK) asm volatile("cp.async.wait_group 1;" ::: "memory");
        else                 asm volatile("cp.async.wait_group 0;" ::: "memory");
        __syncthreads();
        if (kc + 2 < NCHUNK) issue(kc + 2);

        const uint32_t stA = sbase + (kc % 3) * 32768;
        const uint32_t stB = stA + 16384;

        auto ldfrags = [&](int kk, int pb) {
#pragma unroll
            for (int mi = 0; mi < 4; mi++) {
                uint32_t off = (arow + mi * 16) * 128u + kk * 32u + akb;
                ldsm_x4(afr[pb][mi], stA + (off ^ ((off >> 3) & 0x70u)));
            }
#pragma unroll
            for (int nj2 = 0; nj2 < 2; nj2++) {
                uint32_t off = (brow + nj2 * 16) * 128u + kk * 32u + bkb;
                ldsm_x4(bfr[pb][nj2], stB + (off ^ ((off >> 3) & 0x70u)));
            }
        };

        ldfrags(0, 0);
#pragma unroll
        for (int kk = 0; kk < 4; kk++) {
            const int cur = kk & 1;
            if (kk < 3) ldfrags(kk + 1, cur ^ 1);
#pragma unroll
            for (int mi = 0; mi < 4; mi++)
#pragma unroll
                for (int nj = 0; nj < 4; nj++)
                    mma16816(acc[mi][nj], afr[cur][mi],
                             bfr[cur][nj >> 1][(nj & 1) * 2], bfr[cur][nj >> 1][(nj & 1) * 2 + 1]);
        }
    }

    // ----- epilogue -----
    if (MODE == 1) {
        const int lrow = lane >> 2;
        const int lcol = (lane & 3) * 2;
#pragma unroll
        for (int mi = 0; mi < 4; mi++)
#pragma unroll
            for (int nj = 0; nj < 4; nj++) {
                int row0 = m0 + w_m + mi * 16 + lrow;
                int col  = n0 + w_n + nj * 8 + lcol;
                float b0 = __ldg(&biasO[col]), b1 = __ldg(&biasO[col + 1]);
                *(float2*)&Cout[(size_t)row0 * NOUT + col] =
                    make_float2(acc[mi][nj][0] + b0, acc[mi][nj][1] + b1);
                *(float2*)&Cout[(size_t)(row0 + 8) * NOUT + col] =
                    make_float2(acc[mi][nj][2] + b0, acc[mi][nj][3] + b1);
            }
    } else {
        // fused LSTM pointwise. cols are gate-interleaved: n' = 4*unit + gate.
        // lane pair (l, l^1): even member holds (i,f), odd holds (g,o) of the same unit.
        __nv_bfloat16* dstA = g_Ah[par ^ 1];
        const int lrow = lane >> 2;
        const int lcol = (lane & 3) * 2;
        const bool evenlane = (lane & 1) == 0;
#pragma unroll
        for (int mi = 0; mi < 4; mi++)
#pragma unroll
            for (int nj = 0; nj < 4; nj++) {
                int col = n0 + w_n + nj * 8 + lcol;
                float b0 = __ldg(&g_bias[col]), b1 = __ldg(&g_bias[col + 1]);
                float a0 = acc[mi][nj][0] + b0;
                float a1 = acc[mi][nj][1] + b1;
                float a2 = acc[mi][nj][2] + b0;
                float a3 = acc[mi][nj][3] + b1;
                float p0 = __shfl_xor_sync(0xffffffffu, a0, 1);
                float p1 = __shfl_xor_sync(0xffffffffu, a1, 1);
                float p2 = __shfl_xor_sync(0xffffffffu, a2, 1);
                float p3 = __shfl_xor_sync(0xffffffffu, a3, 1);
                float i_, f_, g_, o_;
                int b;
                if (evenlane) { i_ = a0; f_ = a1; g_ = p0; o_ = p1; b = m0 + w_m + mi * 16 + lrow; }
                else          { i_ = p2; f_ = p3; g_ = a2; o_ = a3; b = m0 + w_m + mi * 16 + lrow + 8; }
                int u = ((n0 + w_n) >> 2) + nj * 2 + ((lane & 3) >> 1);
                i_ = sigmoidf_(i_);
                f_ = sigmoidf_(f_);
                g_ = tanhf(g_);
                o_ = sigmoidf_(o_);
                float cn = f_ * g_c[b * HIDD + u] + i_ * g_;
                g_c[b * HIDD + u] = cn;
                float h = o_ * tanhf(cn);
                __nv_bfloat16 hh, hl; split_bf16(h, hh, hl);
                __nv_bfloat16* dr = dstA + (size_t)b * KO;
                dr[u] = hh; dr[HIDD + u] = hl; dr[2 * HIDD + u] = hh;
            }
    }
}

// ---------------- launch ----------------
extern "C" void kernel_launch(void* const* d_in, const int* in_sizes, int n_in,
                              void* d_out, int out_size) {
    const int*   m     = (const int*)  d_in[0];
    const float* emb   = (const float*)d_in[1];
    const float* W_ih  = (const float*)d_in[2];
    const float* W_hh  = (const float*)d_in[3];
    const float* b_ih  = (const float*)d_in[4];
    const float* b_hh  = (const float*)d_in[5];
    const float* W_out = (const float*)d_in[6];
    const float* b_out = (const float*)d_in[7];
    float* out = (float*)d_out;

    cudaFuncSetAttribute(mma_gemm<0>, cudaFuncAttributeMaxDynamicSharedMemorySize, SMEM_DYN);
    cudaFuncSetAttribute(mma_gemm<1>, cudaFuncAttributeMaxDynamicSharedMemorySize, SMEM_DYN);

    init_state_kernel<<<786432 / 256, 256>>>();
    bias_kernel<<<NG / 256, 256>>>(b_ih, b_hh);
    conv_wg_kernel<<<(NG * KIN) / 256, 256>>>(W_ih, W_hh);
    conv_wo_kernel<<<(NOUT * HIDD) / 256, 256>>>(W_out);
    emb_precompute_kernel<<<(unsigned)(((size_t)TT * BB * EMBD) / 256), 256>>>(m, emb);

    for (int t = 0; t < TT; t++) {
        mma_gemm<0><<<dim3(NG / 128, BB / 128), 256, SMEM_DYN>>>(nullptr, nullptr, t, t & 1);
    }
    // after t=63 (odd), new h lives in g_Ah[0]
    mma_gemm<1><<<dim3(NOUT / 128, BB / 128), 256, SMEM_DYN>>>(out, b_out, 0, 0);
}

// round 9
// speedup vs baseline: 1.1558x; 1.1558x over previous
#include <cuda_runtime.h>
#include <cuda_bf16.h>
#include <math.h>
#include <stdint.h>

// ---------------- problem constants ----------------
#define BB    512
#define TT    64
#define EMBD  512
#define HIDD  1024
#define NG    4096
#define NOUT  2048
#define KIN   (EMBD + HIDD)     // 1536
#define KG    (3 * KIN)         // 4608  (split K', gates)
#define KO    (3 * HIDD)        // 3072  (split K', h piece / output proj)
#define NCHUNK_G (KG / 64)      // 72  (chunks 0..23 emb piece, 24..71 h piece)
#define NCHUNK_O (KO / 64)      // 48
#define SMEM_DYN (3 * 32768 + 256)

// ---------------- persistent device scratch ----------------
__device__ float g_c[BB * HIDD];
__device__ float g_gates[BB * NG];
__device__ __align__(16) __nv_bfloat16 g_Ah[2][BB * KO];               // [hh|hl|hh] rows, ping-pong
__device__ __align__(16) __nv_bfloat16 g_Aemb[(size_t)TT * BB * KIN];  // per (t,b): [xh|xl|xh]
__device__ __align__(16) __nv_bfloat16 g_Wg[(size_t)NG * KG];
__device__ __align__(16) __nv_bfloat16 g_Wo[(size_t)NOUT * KO];

// ---------------- helpers ----------------
__device__ __forceinline__ uint32_t smem_u32(const void* p) {
    uint32_t a;
    asm("{ .reg .u64 t; cvta.to.shared.u64 t, %1; cvt.u32.u64 %0, t; }" : "=r"(a) : "l"(p));
    return a;
}
__device__ __forceinline__ void split_bf16(float v, __nv_bfloat16& hi, __nv_bfloat16& lo) {
    hi = __float2bfloat16(v);
    lo = __float2bfloat16(v - __bfloat162float(hi));
}
__device__ __forceinline__ void cp_async16(uint32_t dst, const void* src) {
    asm volatile("cp.async.cg.shared.global [%0], [%1], 16;" :: "r"(dst), "l"(src));
}
__device__ __forceinline__ void cp_commit() {
    asm volatile("cp.async.commit_group;" ::: "memory");
}
__device__ __forceinline__ void ldsm_x4(uint32_t* r, uint32_t addr) {
    asm volatile("ldmatrix.sync.aligned.m8n8.x4.shared.b16 {%0,%1,%2,%3}, [%4];"
                 : "=r"(r[0]), "=r"(r[1]), "=r"(r[2]), "=r"(r[3]) : "r"(addr));
}
__device__ __forceinline__ void mma16816(float* d, const uint32_t* a, uint32_t b0, uint32_t b1) {
    asm volatile(
        "mma.sync.aligned.m16n8k16.row.col.f32.bf16.bf16.f32 "
        "{%0,%1,%2,%3}, {%4,%5,%6,%7}, {%8,%9}, {%0,%1,%2,%3};"
        : "+f"(d[0]), "+f"(d[1]), "+f"(d[2]), "+f"(d[3])
        : "r"(a[0]), "r"(a[1]), "r"(a[2]), "r"(a[3]), "r"(b0), "r"(b1));
}
__device__ __forceinline__ float sigmoidf_(float x) { return 1.0f / (1.0f + expf(-x)); }

// ---------------- setup kernels ----------------
__global__ void init_state_kernel() {
    int i = blockIdx.x * 256 + threadIdx.x;     // grid covers 786432
    if (i < BB * HIDD) g_c[i] = 0.0f;
    ((uint32_t*)g_Ah)[i] = 0u;                  // zeros both ping-pong h buffers
}

// W'g row n: [Wih_h(512) | Wih_h | Wih_l | Whh_h(1024) | Whh_h | Whh_l]
__global__ void conv_wg_kernel(const float* __restrict__ W_ih, const float* __restrict__ W_hh) {
    int idx = blockIdx.x * 256 + threadIdx.x;   // NG*KIN
    int n = idx / KIN, k = idx - n * KIN;
    size_t r = (size_t)n * KG;
    if (k < EMBD) {
        __nv_bfloat16 hi, lo; split_bf16(W_ih[(size_t)n * EMBD + k], hi, lo);
        g_Wg[r + k] = hi; g_Wg[r + EMBD + k] = hi; g_Wg[r + 2 * EMBD + k] = lo;
    } else {
        int kh = k - EMBD;
        __nv_bfloat16 hi, lo; split_bf16(W_hh[(size_t)n * HIDD + kh], hi, lo);
        g_Wg[r + 3 * EMBD + kh] = hi;
        g_Wg[r + 3 * EMBD + HIDD + kh] = hi;
        g_Wg[r + 3 * EMBD + 2 * HIDD + kh] = lo;
    }
}

__global__ void conv_wo_kernel(const float* __restrict__ W_out) {
    int idx = blockIdx.x * 256 + threadIdx.x;   // NOUT*HIDD
    int n = idx / HIDD, k = idx - n * HIDD;
    __nv_bfloat16 hi, lo; split_bf16(W_out[(size_t)n * HIDD + k], hi, lo);
    size_t r = (size_t)n * KO;
    g_Wo[r + k] = hi; g_Wo[r + HIDD + k] = hi; g_Wo[r + 2 * HIDD + k] = lo;
}

// Precompute x-part of A' for all steps: per (t,b): [xh | xl | xh]
__global__ void emb_precompute_kernel(const int* __restrict__ tok, const float* __restrict__ emb) {
    size_t idx = (size_t)blockIdx.x * 256 + threadIdx.x;   // TT*BB*EMBD
    int t = (int)(idx / (BB * EMBD));
    int rem = (int)(idx - (size_t)t * BB * EMBD);
    int b = rem / EMBD, k = rem - b * EMBD;
    float v = emb[(size_t)tok[b * TT + t] * EMBD + k];
    __nv_bfloat16 hi, lo; split_bf16(v, hi, lo);
    size_t r = ((size_t)t * BB + b) * KIN;
    g_Aemb[r + k] = hi; g_Aemb[r + EMBD + k] = lo; g_Aemb[r + 2 * EMBD + k] = hi;
}

// ---------------- mma.sync GEMM ----------------
// CTA 128x128, 8 warps (2x4), warp tile 64x32, K-slab 64 (128B rows, SW128 swizzle),
// 3-stage cp.async, ONE __syncthreads per chunk.
template <int MODE>   // 0 = gates (C=g_gates), 1 = output (C=Cout, +bias)
__global__ __launch_bounds__(256, 1) void mma_gemm(float* __restrict__ Cout,
                                                   const float* __restrict__ biasO,
                                                   int t, int par) {
    constexpr int NCHUNK = (MODE == 0) ? NCHUNK_G : NCHUNK_O;
    constexpr int KLB    = (MODE == 0) ? KG : KO;
    constexpr int LDC    = (MODE == 0) ? NG : NOUT;
    const __nv_bfloat16* Bw = (MODE == 0) ? g_Wg : g_Wo;
    float* C = (MODE == 0) ? g_gates : Cout;

    extern __shared__ char dyn[];
    const uint32_t sbase = (smem_u32(dyn) + 127u) & ~127u;

    const int tid  = threadIdx.x;
    const int wid  = tid >> 5, lane = tid & 31;
    const int m0 = blockIdx.y * 128, n0 = blockIdx.x * 128;
    const int w_m = (wid >> 2) * 64;
    const int w_n = (wid & 3) * 32;

    // ----- cp.async loader -----
    const int lr  = tid >> 3;         // 0..31
    const int lsB = (tid & 7) * 16;   // byte seg within 128B row
    const __nv_bfloat16* Ah = g_Ah[par];
    auto issue = [&](int kc) {
        const uint32_t st = sbase + (kc % 3) * 32768;
        const __nv_bfloat16* ag;
        size_t klda;
        if (MODE == 0 && kc < 24) {
            ag = g_Aemb + ((size_t)t * BB + (m0 + lr)) * KIN + kc * 64 + (lsB >> 1);
            klda = KIN;
        } else {
            int kh = (MODE == 0) ? (kc - 24) : kc;
            ag = Ah + (size_t)(m0 + lr) * KO + kh * 64 + (lsB >> 1);
            klda = KO;
        }
        const __nv_bfloat16* bg = Bw + (size_t)(n0 + lr) * KLB + kc * 64 + (lsB >> 1);
#pragma unroll
        for (int i = 0; i < 4; i++) {
            uint32_t off = (uint32_t)(lr + i * 32) * 128u + (uint32_t)lsB;
            uint32_t sw  = off ^ ((off >> 3) & 0x70u);
            cp_async16(st + sw, ag + (size_t)i * 32 * klda);
            cp_async16(st + 16384 + sw, bg + (size_t)i * 32 * KLB);
        }
        cp_commit();
    };

    // ----- per-lane ldmatrix base offsets (pre-swizzle) -----
    const int q  = lane >> 3;
    const int r8 = lane & 7;
    const uint32_t arow = (uint32_t)(w_m + (q & 1) * 8 + r8);
    const uint32_t akb  = (uint32_t)((q >> 1) * 16);
    const uint32_t brow = (uint32_t)(w_n + (q >> 1) * 8 + r8);
    const uint32_t bkb  = (uint32_t)((q & 1) * 16);

    float acc[4][4][4];
#pragma unroll
    for (int i = 0; i < 4; i++)
#pragma unroll
        for (int j = 0; j < 4; j++)
#pragma unroll
            for (int v = 0; v < 4; v++) acc[i][j][v] = 0.0f;

    issue(0);
    issue(1);

    for (int kc = 0; kc < NCHUNK; kc++) {
        if (kc + 1 < NCHUNK) asm volatile("cp.async.wait_group 1;" ::: "memory");
        else                 asm volatile("cp.async.wait_group 0;" ::: "memory");
        __syncthreads();
        if (kc + 2 < NCHUNK) issue(kc + 2);

        const uint32_t stA = sbase + (kc % 3) * 32768;
        const uint32_t stB = stA + 16384;

#pragma unroll
        for (int kk = 0; kk < 4; kk++) {
            uint32_t afr[4][4];
#pragma unroll
            for (int mi = 0; mi < 4; mi++) {
                uint32_t off = (arow + mi * 16) * 128u + kk * 32u + akb;
                ldsm_x4(afr[mi], stA + (off ^ ((off >> 3) & 0x70u)));
            }
            uint32_t bfr[2][4];
#pragma unroll
            for (int nj2 = 0; nj2 < 2; nj2++) {
                uint32_t off = (brow + nj2 * 16) * 128u + kk * 32u + bkb;
                ldsm_x4(bfr[nj2], stB + (off ^ ((off >> 3) & 0x70u)));
            }
#pragma unroll
            for (int mi = 0; mi < 4; mi++)
#pragma unroll
                for (int nj = 0; nj < 4; nj++)
                    mma16816(acc[mi][nj], afr[mi],
                             bfr[nj >> 1][(nj & 1) * 2], bfr[nj >> 1][(nj & 1) * 2 + 1]);
        }
    }

    // ----- epilogue (plain coalesced f32 stores) -----
    const int lrow = lane >> 2;
    const int lcol = (lane & 3) * 2;
#pragma unroll
    for (int mi = 0; mi < 4; mi++) {
#pragma unroll
        for (int nj = 0; nj < 4; nj++) {
            int row0 = m0 + w_m + mi * 16 + lrow;
            int col  = n0 + w_n + nj * 8 + lcol;
            float b0 = 0.0f, b1 = 0.0f;
            if (MODE == 1) { b0 = __ldg(&biasO[col]); b1 = __ldg(&biasO[col + 1]); }
            *(float2*)&C[(size_t)row0 * LDC + col] =
                make_float2(acc[mi][nj][0] + b0, acc[mi][nj][1] + b1);
            *(float2*)&C[(size_t)(row0 + 8) * LDC + col] =
                make_float2(acc[mi][nj][2] + b0, acc[mi][nj][3] + b1);
        }
    }
}

// ---------------- LSTM pointwise: gates -> c, h (h written in split form) ----------------
__global__ void lstm_update_kernel(const float* __restrict__ b_ih, const float* __restrict__ b_hh,
                                   int dst) {
    int idx = blockIdx.x * blockDim.x + threadIdx.x;  // < BB*HIDD
    int b = idx >> 10;
    int j = idx & (HIDD - 1);
    const float* gb = g_gates + (size_t)b * NG;
    float xi = gb[j]            + b_ih[j]            + b_hh[j];
    float xf = gb[j +     HIDD] + b_ih[j +     HIDD] + b_hh[j +     HIDD];
    float xg = gb[j + 2 * HIDD] + b_ih[j + 2 * HIDD] + b_hh[j + 2 * HIDD];
    float xo = gb[j + 3 * HIDD] + b_ih[j + 3 * HIDD] + b_hh[j + 3 * HIDD];
    float i_ = sigmoidf_(xi);
    float f_ = sigmoidf_(xf);
    float g_ = tanhf(xg);
    float o_ = sigmoidf_(xo);
    float c_ = f_ * g_c[idx] + i_ * g_;
    g_c[idx] = c_;
    float h = o_ * tanhf(c_);
    __nv_bfloat16 hh, hl; split_bf16(h, hh, hl);
    __nv_bfloat16* dr = g_Ah[dst] + (size_t)b * KO;
    dr[j] = hh; dr[HIDD + j] = hl; dr[2 * HIDD + j] = hh;
}

// ---------------- launch ----------------
extern "C" void kernel_launch(void* const* d_in, const int* in_sizes, int n_in,
                              void* d_out, int out_size) {
    const int*   m     = (const int*)  d_in[0];
    const float* emb   = (const float*)d_in[1];
    const float* W_ih  = (const float*)d_in[2];
    const float* W_hh  = (const float*)d_in[3];
    const float* b_ih  = (const float*)d_in[4];
    const float* b_hh  = (const float*)d_in[5];
    const float* W_out = (const float*)d_in[6];
    const float* b_out = (const float*)d_in[7];
    float* out = (float*)d_out;

    cudaFuncSetAttribute(mma_gemm<0>, cudaFuncAttributeMaxDynamicSharedMemorySize, SMEM_DYN);
    cudaFuncSetAttribute(mma_gemm<1>, cudaFuncAttributeMaxDynamicSharedMemorySize, SMEM_DYN);

    init_state_kernel<<<786432 / 256, 256>>>();
    conv_wg_kernel<<<(NG * KIN) / 256, 256>>>(W_ih, W_hh);
    conv_wo_kernel<<<(NOUT * HIDD) / 256, 256>>>(W_out);
    emb_precompute_kernel<<<(unsigned)(((size_t)TT * BB * EMBD) / 256), 256>>>(m, emb);

    for (int t = 0; t < TT; t++) {
        mma_gemm<0><<<dim3(NG / 128, BB / 128), 256, SMEM_DYN>>>(nullptr, nullptr, t, t & 1);
        lstm_update_kernel<<<(BB * HIDD) / 256, 256>>>(b_ih, b_hh, (t & 1) ^ 1);
    }
    // after t=63 (t&1=1, dst=0): final h lives in g_Ah[0]
    mma_gemm<1><<<dim3(NOUT / 128, BB / 128), 256, SMEM_DYN>>>(out, b_out, 0, 0);
}

// round 10
// speedup vs baseline: 2.7655x; 2.3928x over previous
#include <cuda_runtime.h>
#include <cuda_fp16.h>
#include <math.h>
#include <stdint.h>

// ---------------- problem constants ----------------
#define BB    512
#define TT    64
#define EMBD  512
#define HIDD  1024
#define NG    4096
#define NOUT  2048
#define KIN   (EMBD + HIDD)     // 1536  (gates GEMM K: [x | h])
#define NCHUNK_G (KIN / 64)     // 24  (chunks 0..7 emb piece, 8..23 h piece)
#define NCHUNK_O (HIDD / 64)    // 16
#define SMEM_DYN (3 * 32768 + 256)

// ---------------- persistent device scratch ----------------
__device__ float g_c[BB * HIDD];
__device__ float g_gates[BB * NG];
__device__ __align__(16) __half g_Ah[2][BB * HIDD];               // h (fp16), ping-pong
__device__ __align__(16) __half g_Aemb[(size_t)TT * BB * EMBD];   // x_t (fp16), all steps
__device__ __align__(16) __half g_Wg[(size_t)NG * KIN];           // rows: [Wih(512) | Whh(1024)]
__device__ __align__(16) __half g_Wo[(size_t)NOUT * HIDD];

// ---------------- helpers ----------------
__device__ __forceinline__ uint32_t smem_u32(const void* p) {
    uint32_t a;
    asm("{ .reg .u64 t; cvta.to.shared.u64 t, %1; cvt.u32.u64 %0, t; }" : "=r"(a) : "l"(p));
    return a;
}
__device__ __forceinline__ void cp_async16(uint32_t dst, const void* src) {
    asm volatile("cp.async.cg.shared.global [%0], [%1], 16;" :: "r"(dst), "l"(src));
}
__device__ __forceinline__ void cp_commit() {
    asm volatile("cp.async.commit_group;" ::: "memory");
}
__device__ __forceinline__ void ldsm_x4(uint32_t* r, uint32_t addr) {
    asm volatile("ldmatrix.sync.aligned.m8n8.x4.shared.b16 {%0,%1,%2,%3}, [%4];"
                 : "=r"(r[0]), "=r"(r[1]), "=r"(r[2]), "=r"(r[3]) : "r"(addr));
}
__device__ __forceinline__ void mma16816(float* d, const uint32_t* a, uint32_t b0, uint32_t b1) {
    asm volatile(
        "mma.sync.aligned.m16n8k16.row.col.f32.f16.f16.f32 "
        "{%0,%1,%2,%3}, {%4,%5,%6,%7}, {%8,%9}, {%0,%1,%2,%3};"
        : "+f"(d[0]), "+f"(d[1]), "+f"(d[2]), "+f"(d[3])
        : "r"(a[0]), "r"(a[1]), "r"(a[2]), "r"(a[3]), "r"(b0), "r"(b1));
}
__device__ __forceinline__ float sigmoidf_(float x) { return 1.0f / (1.0f + expf(-x)); }

// ---------------- setup kernels ----------------
__global__ void init_state_kernel() {
    int i = blockIdx.x * 256 + threadIdx.x;     // grid covers 524288
    g_c[i] = 0.0f;                              // BB*HIDD floats
    ((uint32_t*)g_Ah)[i] = 0u;                  // 2*BB*HIDD halves = 524288 u32
}

// W'g row n: [Wih(512) | Whh(1024)] fp16
__global__ void conv_wg_kernel(const float* __restrict__ W_ih, const float* __restrict__ W_hh) {
    int idx = blockIdx.x * 256 + threadIdx.x;   // NG*KIN
    int n = idx / KIN, k = idx - n * KIN;
    float w = (k < EMBD) ? W_ih[(size_t)n * EMBD + k] : W_hh[(size_t)n * HIDD + (k - EMBD)];
    g_Wg[(size_t)n * KIN + k] = __float2half(w);
}

__global__ void conv_wo_kernel(const float* __restrict__ W_out) {
    int idx = blockIdx.x * 256 + threadIdx.x;   // NOUT*HIDD
    g_Wo[idx] = __float2half(W_out[idx]);
}

// Precompute x_t (fp16) for all steps
__global__ void emb_precompute_kernel(const int* __restrict__ tok, const float* __restrict__ emb) {
    size_t idx = (size_t)blockIdx.x * 256 + threadIdx.x;   // TT*BB*EMBD
    int t = (int)(idx / (BB * EMBD));
    int rem = (int)(idx - (size_t)t * BB * EMBD);
    int b = rem / EMBD, k = rem - b * EMBD;
    float v = emb[(size_t)tok[b * TT + t] * EMBD + k];
    g_Aemb[((size_t)t * BB + b) * EMBD + k] = __float2half(v);
}

// ---------------- mma.sync GEMM ----------------
// CTA 128x128, 8 warps (2x4), warp tile 64x32, K-slab 64 (128B rows, SW128 swizzle),
// 3-stage cp.async, ONE __syncthreads per chunk. fp16 HMMA, f32 accumulation.
template <int MODE>   // 0 = gates (C=g_gates), 1 = output (C=Cout, +bias)
__global__ __launch_bounds__(256, 1) void mma_gemm(float* __restrict__ Cout,
                                                   const float* __restrict__ biasO,
                                                   int t, int par) {
    constexpr int NCHUNK = (MODE == 0) ? NCHUNK_G : NCHUNK_O;
    constexpr int KLB    = (MODE == 0) ? KIN : HIDD;
    constexpr int LDC    = (MODE == 0) ? NG : NOUT;
    const __half* Bw = (MODE == 0) ? g_Wg : g_Wo;
    float* C = (MODE == 0) ? g_gates : Cout;

    extern __shared__ char dyn[];
    const uint32_t sbase = (smem_u32(dyn) + 127u) & ~127u;

    const int tid  = threadIdx.x;
    const int wid  = tid >> 5, lane = tid & 31;
    const int m0 = blockIdx.y * 128, n0 = blockIdx.x * 128;
    const int w_m = (wid >> 2) * 64;
    const int w_n = (wid & 3) * 32;

    // ----- cp.async loader -----
    const int lr  = tid >> 3;         // 0..31
    const int lsB = (tid & 7) * 16;   // byte seg within 128B row
    const __half* Ah = g_Ah[par];
    auto issue = [&](int kc) {
        const uint32_t st = sbase + (kc % 3) * 32768;
        const __half* ag;
        size_t klda;
        if (MODE == 0 && kc < 8) {
            ag = g_Aemb + ((size_t)t * BB + (m0 + lr)) * EMBD + kc * 64 + (lsB >> 1);
            klda = EMBD;
        } else {
            int kh = (MODE == 0) ? (kc - 8) : kc;
            ag = Ah + (size_t)(m0 + lr) * HIDD + kh * 64 + (lsB >> 1);
            klda = HIDD;
        }
        const __half* bg = Bw + (size_t)(n0 + lr) * KLB + kc * 64 + (lsB >> 1);
#pragma unroll
        for (int i = 0; i < 4; i++) {
            uint32_t off = (uint32_t)(lr + i * 32) * 128u + (uint32_t)lsB;
            uint32_t sw  = off ^ ((off >> 3) & 0x70u);
            cp_async16(st + sw, ag + (size_t)i * 32 * klda);
            cp_async16(st + 16384 + sw, bg + (size_t)i * 32 * KLB);
        }
        cp_commit();
    };

    // ----- per-lane ldmatrix base offsets (pre-swizzle) -----
    const int q  = lane >> 3;
    const int r8 = lane & 7;
    const uint32_t arow = (uint32_t)(w_m + (q & 1) * 8 + r8);
    const uint32_t akb  = (uint32_t)((q >> 1) * 16);
    const uint32_t brow = (uint32_t)(w_n + (q >> 1) * 8 + r8);
    const uint32_t bkb  = (uint32_t)((q & 1) * 16);

    float acc[4][4][4];
#pragma unroll
    for (int i = 0; i < 4; i++)
#pragma unroll
        for (int j = 0; j < 4; j++)
#pragma unroll
            for (int v = 0; v < 4; v++) acc[i][j][v] = 0.0f;

    issue(0);
    issue(1);

    for (int kc = 0; kc < NCHUNK; kc++) {
        if (kc + 1 < NCHUNK) asm volatile("cp.async.wait_group 1;" ::: "memory");
        else                 asm volatile("cp.async.wait_group 0;" ::: "memory");
        __syncthreads();
        if (kc + 2 < NCHUNK) issue(kc + 2);

        const uint32_t stA = sbase + (kc % 3) * 32768;
        const uint32_t stB = stA + 16384;

#pragma unroll
        for (int kk = 0; kk < 4; kk++) {
            uint32_t afr[4][4];
#pragma unroll
            for (int mi = 0; mi < 4; mi++) {
                uint32_t off = (arow + mi * 16) * 128u + kk * 32u + akb;
                ldsm_x4(afr[mi], stA + (off ^ ((off >> 3) & 0x70u)));
            }
            uint32_t bfr[2][4];
#pragma unroll
            for (int nj2 = 0; nj2 < 2; nj2++) {
                uint32_t off = (brow + nj2 * 16) * 128u + kk * 32u + bkb;
                ldsm_x4(bfr[nj2], stB + (off ^ ((off >> 3) & 0x70u)));
            }
#pragma unroll
            for (int mi = 0; mi < 4; mi++)
#pragma unroll
                for (int nj = 0; nj < 4; nj++)
                    mma16816(acc[mi][nj], afr[mi],
                             bfr[nj >> 1][(nj & 1) * 2], bfr[nj >> 1][(nj & 1) * 2 + 1]);
        }
    }

    // ----- epilogue (coalesced f32 stores) -----
    const int lrow = lane >> 2;
    const int lcol = (lane & 3) * 2;
#pragma unroll
    for (int mi = 0; mi < 4; mi++) {
#pragma unroll
        for (int nj = 0; nj < 4; nj++) {
            int row0 = m0 + w_m + mi * 16 + lrow;
            int col  = n0 + w_n + nj * 8 + lcol;
            float b0 = 0.0f, b1 = 0.0f;
            if (MODE == 1) { b0 = __ldg(&biasO[col]); b1 = __ldg(&biasO[col + 1]); }
            *(float2*)&C[(size_t)row0 * LDC + col] =
                make_float2(acc[mi][nj][0] + b0, acc[mi][nj][1] + b1);
            *(float2*)&C[(size_t)(row0 + 8) * LDC + col] =
                make_float2(acc[mi][nj][2] + b0, acc[mi][nj][3] + b1);
        }
    }
}

// ---------------- LSTM pointwise: gates -> c, h (h written as fp16) ----------------
__global__ void lstm_update_kernel(const float* __restrict__ b_ih, const float* __restrict__ b_hh,
                                   int dst) {
    int idx = blockIdx.x * blockDim.x + threadIdx.x;  // < BB*HIDD
    int b = idx >> 10;
    int j = idx & (HIDD - 1);
    const float* gb = g_gates + (size_t)b * NG;
    float xi = gb[j]            + b_ih[j]            + b_hh[j];
    float xf = gb[j +     HIDD] + b_ih[j +     HIDD] + b_hh[j +     HIDD];
    float xg = gb[j + 2 * HIDD] + b_ih[j + 2 * HIDD] + b_hh[j + 2 * HIDD];
    float xo = gb[j + 3 * HIDD] + b_ih[j + 3 * HIDD] + b_hh[j + 3 * HIDD];
    float i_ = sigmoidf_(xi);
    float f_ = sigmoidf_(xf);
    float g_ = tanhf(xg);
    float o_ = sigmoidf_(xo);
    float c_ = f_ * g_c[idx] + i_ * g_;
    g_c[idx] = c_;
    float h = o_ * tanhf(c_);
    g_Ah[dst][idx] = __float2half(h);
}

// ---------------- launch ----------------
extern "C" void kernel_launch(void* const* d_in, const int* in_sizes, int n_in,
                              void* d_out, int out_size) {
    const int*   m     = (const int*)  d_in[0];
    const float* emb   = (const float*)d_in[1];
    const float* W_ih  = (const float*)d_in[2];
    const float* W_hh  = (const float*)d_in[3];
    const float* b_ih  = (const float*)d_in[4];
    const float* b_hh  = (const float*)d_in[5];
    const float* W_out = (const float*)d_in[6];
    const float* b_out = (const float*)d_in[7];
    float* out = (float*)d_out;

    cudaFuncSetAttribute(mma_gemm<0>, cudaFuncAttributeMaxDynamicSharedMemorySize, SMEM_DYN);
    cudaFuncSetAttribute(mma_gemm<1>, cudaFuncAttributeMaxDynamicSharedMemorySize, SMEM_DYN);

    init_state_kernel<<<(BB * HIDD) / 256, 256>>>();
    conv_wg_kernel<<<(NG * KIN) / 256, 256>>>(W_ih, W_hh);
    conv_wo_kernel<<<(NOUT * HIDD) / 256, 256>>>(W_out);
    emb_precompute_kernel<<<(unsigned)(((size_t)TT * BB * EMBD) / 256), 256>>>(m, emb);

    for (int t = 0; t < TT; t++) {
        mma_gemm<0><<<dim3(NG / 128, BB / 128), 256, SMEM_DYN>>>(nullptr, nullptr, t, t & 1);
        lstm_update_kernel<<<(BB * HIDD) / 256, 256>>>(b_ih, b_hh, (t & 1) ^ 1);
    }
    // after t=63 (t&1=1, dst=0): final h lives in g_Ah[0]
    mma_gemm<1><<<dim3(NOUT / 128, BB / 128), 256, SMEM_DYN>>>(out, b_out, 0, 0);
}

// round 11
// speedup vs baseline: 2.7947x; 1.0106x over previous
#include <cuda_runtime.h>
#include <cuda_fp16.h>
#include <math.h>
#include <stdint.h>

// ---------------- problem constants ----------------
#define BB    512
#define TT    64
#define EMBD  512
#define HIDD  1024
#define NG    4096
#define NOUT  2048
#define KIN   (EMBD + HIDD)     // 1536 (gates GEMM K: [x | h])
#define NCHUNK_G (KIN / 64)     // 24  (chunks 0..7 emb, 8..23 h)
#define NCHUNK_O (HIDD / 64)    // 16
#define NCTA  128               // 32 x 4 persistent grid
#define SMEM_DYN (3 * 32768 + 256)

// ---------------- persistent device scratch ----------------
__device__ float g_bias[NG];                                      // interleaved b_ih+b_hh
__device__ __align__(16) __half g_h16[2][BB * HIDD];              // h (fp16), ping-pong
__device__ __align__(16) __half g_emb16[(size_t)TT * BB * EMBD];  // x_t (fp16), all steps
__device__ __align__(16) __half g_Wg[(size_t)NG * KIN];           // gate-interleaved rows [Wih|Whh]
__device__ __align__(16) __half g_Wo[(size_t)NOUT * HIDD];
__device__ unsigned g_cnt;                                        // grid barrier
__device__ volatile unsigned g_gen;

// ---------------- helpers ----------------
__device__ __forceinline__ uint32_t smem_u32(const void* p) {
    uint32_t a;
    asm("{ .reg .u64 t; cvta.to.shared.u64 t, %1; cvt.u32.u64 %0, t; }" : "=r"(a) : "l"(p));
    return a;
}
__device__ __forceinline__ void cp_async16(uint32_t dst, const void* src) {
    asm volatile("cp.async.cg.shared.global [%0], [%1], 16;" :: "r"(dst), "l"(src));
}
__device__ __forceinline__ void cp_commit() {
    asm volatile("cp.async.commit_group;" ::: "memory");
}
__device__ __forceinline__ void ldsm_x4(uint32_t* r, uint32_t addr) {
    asm volatile("ldmatrix.sync.aligned.m8n8.x4.shared.b16 {%0,%1,%2,%3}, [%4];"
                 : "=r"(r[0]), "=r"(r[1]), "=r"(r[2]), "=r"(r[3]) : "r"(addr));
}
__device__ __forceinline__ void mma16816(float* d, const uint32_t* a, uint32_t b0, uint32_t b1) {
    asm volatile(
        "mma.sync.aligned.m16n8k16.row.col.f32.f16.f16.f32 "
        "{%0,%1,%2,%3}, {%4,%5,%6,%7}, {%8,%9}, {%0,%1,%2,%3};"
        : "+f"(d[0]), "+f"(d[1]), "+f"(d[2]), "+f"(d[3])
        : "r"(a[0]), "r"(a[1]), "r"(a[2]), "r"(a[3]), "r"(b0), "r"(b1));
}
__device__ __forceinline__ float sigmoidf_(float x) { return 1.0f / (1.0f + expf(-x)); }

// ---------------- setup kernels ----------------
__global__ void init_state_kernel() {
    int i = blockIdx.x * 256 + threadIdx.x;     // grid covers 524288 u32 = both h buffers
    ((uint32_t*)g_h16)[i] = 0u;
    if (i == 0) { g_cnt = 0; g_gen = 0; }
}

// interleaved bias: n' = 4u + gate
__global__ void bias_kernel(const float* __restrict__ b_ih, const float* __restrict__ b_hh) {
    int n_ = blockIdx.x * 256 + threadIdx.x;
    int gate = n_ & 3, j = n_ >> 2;
    g_bias[n_] = b_ih[gate * HIDD + j] + b_hh[gate * HIDD + j];
}

// W'g row n' = 4u+gate : [Wih(512) | Whh(1024)] fp16
__global__ void conv_wg_kernel(const float* __restrict__ W_ih, const float* __restrict__ W_hh) {
    int idx = blockIdx.x * 256 + threadIdx.x;   // NG*KIN
    int n_ = idx / KIN, k = idx - n_ * KIN;
    int gate = n_ & 3, j = n_ >> 2;
    int orig = gate * HIDD + j;
    float w = (k < EMBD) ? W_ih[(size_t)orig * EMBD + k] : W_hh[(size_t)orig * HIDD + (k - EMBD)];
    g_Wg[(size_t)n_ * KIN + k] = __float2half(w);
}

__global__ void conv_wo_kernel(const float* __restrict__ W_out) {
    int idx = blockIdx.x * 256 + threadIdx.x;   // NOUT*HIDD
    g_Wo[idx] = __float2half(W_out[idx]);
}

// Precompute x_t (fp16) for all steps
__global__ void emb_precompute_kernel(const int* __restrict__ tok, const float* __restrict__ emb) {
    size_t idx = (size_t)blockIdx.x * 256 + threadIdx.x;   // TT*BB*EMBD
    int t = (int)(idx / (BB * EMBD));
    int rem = (int)(idx - (size_t)t * BB * EMBD);
    int b = rem / EMBD, k = rem - b * EMBD;
    float v = emb[(size_t)tok[b * TT + t] * EMBD + k];
    g_emb16[((size_t)t * BB + b) * EMBD + k] = __float2half(v);
}

// ---------------- persistent LSTM kernel: all 64 steps ----------------
// CTA (bn, bm): batch rows [bm*128, +128), interleaved gate cols [bn*128, +128)
// = hidden units [bn*32, +32). c kept in registers across all steps.
__global__ __launch_bounds__(256, 1) void lstm_persistent_kernel() {
    extern __shared__ char dyn[];
    const uint32_t sbase = (smem_u32(dyn) + 127u) & ~127u;
    __half* hs = (__half*)(dyn + (sbase - smem_u32(dyn)));   // h stage = stage-0 region

    const int tid  = threadIdx.x;
    const int wid  = tid >> 5, lane = tid & 31;
    const int m0 = blockIdx.y * 128, n0 = blockIdx.x * 128;
    const int w_m = (wid >> 2) * 64;
    const int w_n = (wid & 3) * 32;

    // loader mapping
    const int lr  = tid >> 3;
    const int lsB = (tid & 7) * 16;

    // ldmatrix lane offsets (pre-swizzle)
    const int q  = lane >> 3;
    const int r8 = lane & 7;
    const uint32_t arow = (uint32_t)(w_m + (q & 1) * 8 + r8);
    const uint32_t akb  = (uint32_t)((q >> 1) * 16);
    const uint32_t brow = (uint32_t)(w_n + (q >> 1) * 8 + r8);
    const uint32_t bkb  = (uint32_t)((q & 1) * 16);

    // per-thread bias (constant across steps)
    const int lcol = (lane & 3) * 2;
    float bj0[4], bj1[4];
#pragma unroll
    for (int nj = 0; nj < 4; nj++) {
        int col = n0 + w_n + nj * 8 + lcol;
        bj0[nj] = g_bias[col];
        bj1[nj] = g_bias[col + 1];
    }

    const int lrow = lane >> 2;
    const bool evenlane = (lane & 1) == 0;
    // fixed (b_local, u_local) mapping for this thread's 16 results
    const int ul_base = (w_n >> 2) + ((lane & 3) >> 1);   // + nj*2

    float c_reg[4][4];
#pragma unroll
    for (int i = 0; i < 4; i++)
#pragma unroll
        for (int j = 0; j < 4; j++) c_reg[i][j] = 0.0f;

    for (int t = 0; t < TT; t++) {
        const __half* Ah = g_h16[t & 1];

        auto issue = [&](int kc) {
            const uint32_t st = sbase + (kc % 3) * 32768;
            const __half* ag;
            size_t klda;
            if (kc < 8) {
                ag = g_emb16 + ((size_t)t * BB + (m0 + lr)) * EMBD + kc * 64 + (lsB >> 1);
                klda = EMBD;
            } else {
                ag = Ah + (size_t)(m0 + lr) * HIDD + (kc - 8) * 64 + (lsB >> 1);
                klda = HIDD;
            }
            const __half* bg = g_Wg + (size_t)(n0 + lr) * KIN + kc * 64 + (lsB >> 1);
#pragma unroll
            for (int i = 0; i < 4; i++) {
                uint32_t off = (uint32_t)(lr + i * 32) * 128u + (uint32_t)lsB;
                uint32_t sw  = off ^ ((off >> 3) & 0x70u);
                cp_async16(st + sw, ag + (size_t)i * 32 * klda);
                cp_async16(st + 16384 + sw, bg + (size_t)i * 32 * KIN);
            }
            cp_commit();
        };

        float acc[4][4][4];
#pragma unroll
        for (int i = 0; i < 4; i++)
#pragma unroll
            for (int j = 0; j < 4; j++)
#pragma unroll
                for (int v = 0; v < 4; v++) acc[i][j][v] = 0.0f;

        issue(0);
        issue(1);

        for (int kc = 0; kc < NCHUNK_G; kc++) {
            if (kc + 1 < NCHUNK_G) asm volatile("cp.async.wait_group 1;" ::: "memory");
            else                   asm volatile("cp.async.wait_group 0;" ::: "memory");
            __syncthreads();
            if (kc + 2 < NCHUNK_G) issue(kc + 2);

            const uint32_t stA = sbase + (kc % 3) * 32768;
            const uint32_t stB = stA + 16384;

#pragma unroll
            for (int kk = 0; kk < 4; kk++) {
                uint32_t afr[4][4];
#pragma unroll
                for (int mi = 0; mi < 4; mi++) {
                    uint32_t off = (arow + mi * 16) * 128u + kk * 32u + akb;
                    ldsm_x4(afr[mi], stA + (off ^ ((off >> 3) & 0x70u)));
                }
                uint32_t bfr[2][4];
#pragma unroll
                for (int nj2 = 0; nj2 < 2; nj2++) {
                    uint32_t off = (brow + nj2 * 16) * 128u + kk * 32u + bkb;
                    ldsm_x4(bfr[nj2], stB + (off ^ ((off >> 3) & 0x70u)));
                }
#pragma unroll
                for (int mi = 0; mi < 4; mi++)
#pragma unroll
                    for (int nj = 0; nj < 4; nj++)
                        mma16816(acc[mi][nj], afr[mi],
                                 bfr[nj >> 1][(nj & 1) * 2], bfr[nj >> 1][(nj & 1) * 2 + 1]);
            }
        }
        // NOTE: last chunk (23) reads stage 2; hs lives in stage 0 -> no overlap hazard.

        // ----- fused LSTM epilogue (R8-verified pairing) -----
#pragma unroll
        for (int mi = 0; mi < 4; mi++) {
#pragma unroll
            for (int nj = 0; nj < 4; nj++) {
                float a0 = acc[mi][nj][0] + bj0[nj];
                float a1 = acc[mi][nj][1] + bj1[nj];
                float a2 = acc[mi][nj][2] + bj0[nj];
                float a3 = acc[mi][nj][3] + bj1[nj];
                float p0 = __shfl_xor_sync(0xffffffffu, a0, 1);
                float p1 = __shfl_xor_sync(0xffffffffu, a1, 1);
                float p2 = __shfl_xor_sync(0xffffffffu, a2, 1);
                float p3 = __shfl_xor_sync(0xffffffffu, a3, 1);
                float i_, f_, g_, o_;
                int bl;
                if (evenlane) { i_ = a0; f_ = a1; g_ = p0; o_ = p1; bl = w_m + mi * 16 + lrow; }
                else          { i_ = p2; f_ = p3; g_ = a2; o_ = a3; bl = w_m + mi * 16 + lrow + 8; }
                int ul = ul_base + nj * 2;
                i_ = sigmoidf_(i_);
                f_ = sigmoidf_(f_);
                g_ = tanhf(g_);
                o_ = sigmoidf_(o_);
                float cn = f_ * c_reg[mi][nj] + i_ * g_;
                c_reg[mi][nj] = cn;
                hs[bl * 32 + ul] = __float2half(o_ * tanhf(cn));
            }
        }
        __syncthreads();

        // coalesced h store: 128 rows x 32 halves (64B/row) -> g_h16[(t+1)&1]
        __half* hdst = g_h16[(t + 1) & 1];
#pragma unroll
        for (int it = 0; it < 2; it++) {
            int i = tid + it * 256;            // 512 uint4 total
            int row = i >> 2, seg = i & 3;
            uint4 v = ((const uint4*)hs)[i];
            *(uint4*)(hdst + (size_t)(m0 + row) * HIDD + (n0 >> 2) + seg * 8) = v;
        }

        // ----- grid barrier -----
        __syncthreads();
        if (tid == 0) {
            __threadfence();
            if (atomicAdd(&g_cnt, 1u) == NCTA - 1) {
                g_cnt = 0;
                __threadfence();
                g_gen = (unsigned)(t + 1);
            } else {
                while (g_gen < (unsigned)(t + 1)) __nanosleep(64);
                __threadfence();
            }
        }
        __syncthreads();
    }
}

// ---------------- output projection GEMM (fp16 HMMA, f32 out) ----------------
__global__ __launch_bounds__(256, 1) void out_gemm(float* __restrict__ Cout,
                                                   const float* __restrict__ biasO) {
    extern __shared__ char dyn[];
    const uint32_t sbase = (smem_u32(dyn) + 127u) & ~127u;

    const int tid  = threadIdx.x;
    const int wid  = tid >> 5, lane = tid & 31;
    const int m0 = blockIdx.y * 128, n0 = blockIdx.x * 128;
    const int w_m = (wid >> 2) * 64;
    const int w_n = (wid & 3) * 32;

    const int lr  = tid >> 3;
    const int lsB = (tid & 7) * 16;
    const __half* Ah = g_h16[0];   // final h after 64 steps
    auto issue = [&](int kc) {
        const uint32_t st = sbase + (kc % 3) * 32768;
        const __half* ag = Ah + (size_t)(m0 + lr) * HIDD + kc * 64 + (lsB >> 1);
        const __half* bg = g_Wo + (size_t)(n0 + lr) * HIDD + kc * 64 + (lsB >> 1);
#pragma unroll
        for (int i = 0; i < 4; i++) {
            uint32_t off = (uint32_t)(lr + i * 32) * 128u + (uint32_t)lsB;
            uint32_t sw  = off ^ ((off >> 3) & 0x70u);
            cp_async16(st + sw, ag + (size_t)i * 32 * HIDD);
            cp_async16(st + 16384 + sw, bg + (size_t)i * 32 * HIDD);
        }
        cp_commit();
    };

    const int q  = lane >> 3;
    const int r8 = lane & 7;
    const uint32_t arow = (uint32_t)(w_m + (q & 1) * 8 + r8);
    const uint32_t akb  = (uint32_t)((q >> 1) * 16);
    const uint32_t brow = (uint32_t)(w_n + (q >> 1) * 8 + r8);
    const uint32_t bkb  = (uint32_t)((q & 1) * 16);

    float acc[4][4][4];
#pragma unroll
    for (int i = 0; i < 4; i++)
#pragma unroll
        for (int j = 0; j < 4; j++)
#pragma unroll
            for (int v = 0; v < 4; v++) acc[i][j][v] = 0.0f;

    issue(0);
    issue(1);

    for (int kc = 0; kc < NCHUNK_O; kc++) {
        if (kc + 1 < NCHUNK_O) asm volatile("cp.async.wait_group 1;" ::: "memory");
        else                   asm volatile("cp.async.wait_group 0;" ::: "memory");
        __syncthreads();
        if (kc + 2 < NCHUNK_O) issue(kc + 2);

        const uint32_t stA = sbase + (kc % 3) * 32768;
        const uint32_t stB = stA + 16384;

#pragma unroll
        for (int kk = 0; kk < 4; kk++) {
            uint32_t afr[4][4];
#pragma unroll
            for (int mi = 0; mi < 4; mi++) {
                uint32_t off = (arow + mi * 16) * 128u + kk * 32u + akb;
                ldsm_x4(afr[mi], stA + (off ^ ((off >> 3) & 0x70u)));
            }
            uint32_t bfr[2][4];
#pragma unroll
            for (int nj2 = 0; nj2 < 2; nj2++) {
                uint32_t off = (brow + nj2 * 16) * 128u + kk * 32u + bkb;
                ldsm_x4(bfr[nj2], stB + (off ^ ((off >> 3) & 0x70u)));
            }
#pragma unroll
            for (int mi = 0; mi < 4; mi++)
#pragma unroll
                for (int nj = 0; nj < 4; nj++)
                    mma16816(acc[mi][nj], afr[mi],
                             bfr[nj >> 1][(nj & 1) * 2], bfr[nj >> 1][(nj & 1) * 2 + 1]);
        }
    }

    const int lrow = lane >> 2;
    const int lcol = (lane & 3) * 2;
#pragma unroll
    for (int mi = 0; mi < 4; mi++) {
#pragma unroll
        for (int nj = 0; nj < 4; nj++) {
            int row0 = m0 + w_m + mi * 16 + lrow;
            int col  = n0 + w_n + nj * 8 + lcol;
            float b0 = __ldg(&biasO[col]), b1 = __ldg(&biasO[col + 1]);
            *(float2*)&Cout[(size_t)row0 * NOUT + col] =
                make_float2(acc[mi][nj][0] + b0, acc[mi][nj][1] + b1);
            *(float2*)&Cout[(size_t)(row0 + 8) * NOUT + col] =
                make_float2(acc[mi][nj][2] + b0, acc[mi][nj][3] + b1);
        }
    }
}

// ---------------- launch ----------------
extern "C" void kernel_launch(void* const* d_in, const int* in_sizes, int n_in,
                              void* d_out, int out_size) {
    const int*   m     = (const int*)  d_in[0];
    const float* emb   = (const float*)d_in[1];
    const float* W_ih  = (const float*)d_in[2];
    const float* W_hh  = (const float*)d_in[3];
    const float* b_ih  = (const float*)d_in[4];
    const float* b_hh  = (const float*)d_in[5];
    const float* W_out = (const float*)d_in[6];
    const float* b_out = (const float*)d_in[7];
    float* out = (float*)d_out;

    cudaFuncSetAttribute(lstm_persistent_kernel, cudaFuncAttributeMaxDynamicSharedMemorySize, SMEM_DYN);
    cudaFuncSetAttribute(out_gemm, cudaFuncAttributeMaxDynamicSharedMemorySize, SMEM_DYN);

    init_state_kernel<<<(2 * BB * HIDD / 2) / 256, 256>>>();
    bias_kernel<<<NG / 256, 256>>>(b_ih, b_hh);
    conv_wg_kernel<<<(NG * KIN) / 256, 256>>>(W_ih, W_hh);
    conv_wo_kernel<<<(NOUT * HIDD) / 256, 256>>>(W_out);
    emb_precompute_kernel<<<(unsigned)(((size_t)TT * BB * EMBD) / 256), 256>>>(m, emb);

    lstm_persistent_kernel<<<dim3(32, 4), 256, SMEM_DYN>>>();
    out_gemm<<<dim3(NOUT / 128, BB / 128), 256, SMEM_DYN>>>(out, b_out);
}